// round 8
// baseline (speedup 1.0000x reference)
#include <cuda_runtime.h>
#include <cuda_bf16.h>
#include <cstdint>

// Inverse 2x2 Haar synthesis, output-centric, 4 work items per thread
// (16 front-batched loads, MLP=16), corrected compact addressing.
// Input  x: [B=8, 4*C=256, H=256, W=256] fp32  (subband-major: k*C + c)
// Output o: [B=8, C=64, 2H=512, 2W=512] fp32
//
// Work item i = b*2^21 + c*32768 + h*128 + j   (float2-granular, j<128)
//   in_base(float2)  = i + 3*(i & ~(2^21-1))   (batch stride spans 4 subbands)
//   out_base(float4) = 2*i - (i & 127)
// Loads:  4 x LDG.64 per item (subband stride 2,097,152 float2)
// Stores: 2 x STG.128 per item (row stride 128 float4)

static constexpr int      IN_K_STRIDE2 = 64 * 256 * 128;      // 2,097,152 float2
static constexpr int      OW4          = 128;                 // float4 per output row
static constexpr unsigned B_MASK       = ~((1u << 21) - 1u);  // top (batch) bits of item idx
static constexpr unsigned N_ITEMS      = 16777216u;
static constexpr unsigned Q            = N_ITEMS / 4;         // 4,194,304

__device__ __forceinline__ float2 ldcs2(const float2* p) {
    float2 v;
    asm volatile("ld.global.cs.v2.f32 {%0, %1}, [%2];"
                 : "=f"(v.x), "=f"(v.y) : "l"(p));
    return v;
}

__device__ __forceinline__ void stcs4(float4* p, float4 v) {
    asm volatile("st.global.cs.v4.f32 [%0], {%1, %2, %3, %4};"
                 :: "l"(p), "f"(v.x), "f"(v.y), "f"(v.z), "f"(v.w));
}

__device__ __forceinline__ unsigned in_base_of(unsigned item) {
    // i + 3 * (b << 21): input batch stride is 4 subbands wide.
    return item + 3u * (item & B_MASK);
}

__device__ __forceinline__ void haar_item(float4* __restrict__ out,
                                          unsigned item,
                                          float2 ll, float2 lh,
                                          float2 hl, float2 hh)
{
    const float q = 0.25f;

    float s1x = ll.x + lh.x, s2x = hl.x + hh.x;
    float d1x = ll.x - lh.x, d2x = hl.x - hh.x;
    float s1y = ll.y + lh.y, s2y = hl.y + hh.y;
    float d1y = ll.y - lh.y, d2y = hl.y - hh.y;

    float4 r0 = make_float4((s1x + s2x) * q, (s1x - s2x) * q,
                            (s1y + s2y) * q, (s1y - s2y) * q);
    float4 r1 = make_float4((d1x + d2x) * q, (d1x - d2x) * q,
                            (d1y + d2y) * q, (d1y - d2y) * q);

    unsigned out_base = 2u * item - (item & (OW4 - 1));
    stcs4(out + out_base,       r0);
    stcs4(out + out_base + OW4, r1);
}

__global__ __launch_bounds__(256)
void iwt_kernel(const float2* __restrict__ in, float4* __restrict__ out)
{
    unsigned i = blockIdx.x * blockDim.x + threadIdx.x;   // < Q

    unsigned i0 = i;
    unsigned i1 = i + Q;
    unsigned i2 = i + 2 * Q;
    unsigned i3 = i + 3 * Q;

    unsigned a0 = in_base_of(i0);
    unsigned a1 = in_base_of(i1);
    unsigned a2 = in_base_of(i2);
    unsigned a3 = in_base_of(i3);

    // 16 independent loads, all issued before any dependent use.
    float2 ll0 = ldcs2(in + a0 + 0 * IN_K_STRIDE2);
    float2 lh0 = ldcs2(in + a0 + 1 * IN_K_STRIDE2);
    float2 hl0 = ldcs2(in + a0 + 2 * IN_K_STRIDE2);
    float2 hh0 = ldcs2(in + a0 + 3 * IN_K_STRIDE2);
    float2 ll1 = ldcs2(in + a1 + 0 * IN_K_STRIDE2);
    float2 lh1 = ldcs2(in + a1 + 1 * IN_K_STRIDE2);
    float2 hl1 = ldcs2(in + a1 + 2 * IN_K_STRIDE2);
    float2 hh1 = ldcs2(in + a1 + 3 * IN_K_STRIDE2);
    float2 ll2 = ldcs2(in + a2 + 0 * IN_K_STRIDE2);
    float2 lh2 = ldcs2(in + a2 + 1 * IN_K_STRIDE2);
    float2 hl2 = ldcs2(in + a2 + 2 * IN_K_STRIDE2);
    float2 hh2 = ldcs2(in + a2 + 3 * IN_K_STRIDE2);
    float2 ll3 = ldcs2(in + a3 + 0 * IN_K_STRIDE2);
    float2 lh3 = ldcs2(in + a3 + 1 * IN_K_STRIDE2);
    float2 hl3 = ldcs2(in + a3 + 2 * IN_K_STRIDE2);
    float2 hh3 = ldcs2(in + a3 + 3 * IN_K_STRIDE2);

    haar_item(out, i0, ll0, lh0, hl0, hh0);
    haar_item(out, i1, ll1, lh1, hl1, hh1);
    haar_item(out, i2, ll2, lh2, hl2, hh2);
    haar_item(out, i3, ll3, lh3, hl3, hh3);
}

extern "C" void kernel_launch(void* const* d_in, const int* in_sizes, int n_in,
                              void* d_out, int out_size)
{
    const float2* in  = (const float2*)d_in[0];
    float4*       out = (float4*)d_out;

    const int threads = 256;
    const int blocks  = (int)(Q / threads);   // 16384

    iwt_kernel<<<blocks, threads>>>(in, out);
}

// round 12
// speedup vs baseline: 1.0091x; 1.0091x over previous
#include <cuda_runtime.h>
#include <cuda_bf16.h>
#include <cstdint>

// Inverse 2x2 Haar synthesis — best-measured config:
// 2 work items/thread (MLP=8), 512-thread blocks, compact addressing.
// Input  x: [B=8, 4*C=256, H=256, W=256] fp32  (subband-major: k*C + c)
// Output o: [B=8, C=64, 2H=512, 2W=512] fp32
//
// Work item i = b*2^21 + c*32768 + h*128 + j   (float2-granular, j<128)
//   in_base(float2)  = i + 3*(i & ~(2^21-1))   (input batch stride spans 4 subbands)
//   out_base(float4) = 2*i - (i & 127)
// Loads:  4 x LDG.64 per item (subband stride 2,097,152 float2), fully coalesced
// Stores: 2 x STG.128 per item (row stride 128 float4), fully coalesced

static constexpr int      IN_K_STRIDE2 = 64 * 256 * 128;      // 2,097,152 float2
static constexpr int      OW4          = 128;                 // float4 per output row
static constexpr unsigned B_MASK       = ~((1u << 21) - 1u);
static constexpr unsigned N_ITEMS      = 16777216u;
static constexpr unsigned Q            = N_ITEMS / 2;         // 8,388,608

__device__ __forceinline__ float2 ldcs2(const float2* p) {
    float2 v;
    asm volatile("ld.global.cs.v2.f32 {%0, %1}, [%2];"
                 : "=f"(v.x), "=f"(v.y) : "l"(p));
    return v;
}

__device__ __forceinline__ void stcs4(float4* p, float4 v) {
    asm volatile("st.global.cs.v4.f32 [%0], {%1, %2, %3, %4};"
                 :: "l"(p), "f"(v.x), "f"(v.y), "f"(v.z), "f"(v.w));
}

__device__ __forceinline__ unsigned in_base_of(unsigned item) {
    return item + 3u * (item & B_MASK);
}

__device__ __forceinline__ void haar_item(float4* __restrict__ out,
                                          unsigned item,
                                          float2 ll, float2 lh,
                                          float2 hl, float2 hh)
{
    const float q = 0.25f;

    float s1x = ll.x + lh.x, s2x = hl.x + hh.x;
    float d1x = ll.x - lh.x, d2x = hl.x - hh.x;
    float s1y = ll.y + lh.y, s2y = hl.y + hh.y;
    float d1y = ll.y - lh.y, d2y = hl.y - hh.y;

    float4 r0 = make_float4((s1x + s2x) * q, (s1x - s2x) * q,
                            (s1y + s2y) * q, (s1y - s2y) * q);
    float4 r1 = make_float4((d1x + d2x) * q, (d1x - d2x) * q,
                            (d1y + d2y) * q, (d1y - d2y) * q);

    unsigned out_base = 2u * item - (item & (OW4 - 1));
    stcs4(out + out_base,       r0);
    stcs4(out + out_base + OW4, r1);
}

__global__ __launch_bounds__(512)
void iwt_kernel(const float2* __restrict__ in, float4* __restrict__ out)
{
    unsigned i = blockIdx.x * blockDim.x + threadIdx.x;   // < Q

    unsigned i0 = i;
    unsigned i1 = i + Q;

    unsigned a0 = in_base_of(i0);
    unsigned a1 = in_base_of(i1);

    // 8 independent loads issued before any dependent use.
    float2 ll0 = ldcs2(in + a0 + 0 * IN_K_STRIDE2);
    float2 lh0 = ldcs2(in + a0 + 1 * IN_K_STRIDE2);
    float2 hl0 = ldcs2(in + a0 + 2 * IN_K_STRIDE2);
    float2 hh0 = ldcs2(in + a0 + 3 * IN_K_STRIDE2);
    float2 ll1 = ldcs2(in + a1 + 0 * IN_K_STRIDE2);
    float2 lh1 = ldcs2(in + a1 + 1 * IN_K_STRIDE2);
    float2 hl1 = ldcs2(in + a1 + 2 * IN_K_STRIDE2);
    float2 hh1 = ldcs2(in + a1 + 3 * IN_K_STRIDE2);

    haar_item(out, i0, ll0, lh0, hl0, hh0);
    haar_item(out, i1, ll1, lh1, hl1, hh1);
}

extern "C" void kernel_launch(void* const* d_in, const int* in_sizes, int n_in,
                              void* d_out, int out_size)
{
    const float2* in  = (const float2*)d_in[0];
    float4*       out = (float4*)d_out;

    const int threads = 512;
    const int blocks  = (int)(Q / threads);   // 16384

    iwt_kernel<<<blocks, threads>>>(in, out);
}

// round 13
// speedup vs baseline: 1.0201x; 1.0109x over previous
#include <cuda_runtime.h>
#include <cuda_bf16.h>
#include <cstdint>

// Inverse 2x2 Haar synthesis — R2 structure (1 item/thread, 256-thread
// blocks; best measured wall-clock) + compact 2-op addressing.
// Input  x: [B=8, 4*C=256, H=256, W=256] fp32  (subband-major: k*C + c)
// Output o: [B=8, C=64, 2H=512, 2W=512] fp32
//
// Work item i = b*2^21 + c*32768 + h*128 + j   (float2-granular, j<128)
//   in_base(float2)  = i + 3*(i & ~(2^21-1))   (input batch stride spans 4 subbands)
//   out_base(float4) = 2*i - (i & 127)
// Loads:  4 x LDG.64 (float2 per subband, stride 2,097,152), fully coalesced
// Stores: 2 x STG.128 (float4 per output row, row stride 128), fully coalesced

static constexpr int      IN_K_STRIDE2 = 64 * 256 * 128;      // 2,097,152 float2
static constexpr int      OW4          = 128;                 // float4 per output row
static constexpr unsigned B_MASK       = ~((1u << 21) - 1u);
static constexpr unsigned N_ITEMS      = 16777216u;

__device__ __forceinline__ float2 ldcs2(const float2* p) {
    float2 v;
    asm volatile("ld.global.cs.v2.f32 {%0, %1}, [%2];"
                 : "=f"(v.x), "=f"(v.y) : "l"(p));
    return v;
}

__device__ __forceinline__ void stcs4(float4* p, float4 v) {
    asm volatile("st.global.cs.v4.f32 [%0], {%1, %2, %3, %4};"
                 :: "l"(p), "f"(v.x), "f"(v.y), "f"(v.z), "f"(v.w));
}

__global__ __launch_bounds__(256)
void iwt_kernel(const float2* __restrict__ in, float4* __restrict__ out)
{
    unsigned i = blockIdx.x * blockDim.x + threadIdx.x;   // < 2^24

    unsigned in_base = i + 3u * (i & B_MASK);

    float2 ll = ldcs2(in + in_base + 0 * IN_K_STRIDE2);
    float2 lh = ldcs2(in + in_base + 1 * IN_K_STRIDE2);
    float2 hl = ldcs2(in + in_base + 2 * IN_K_STRIDE2);
    float2 hh = ldcs2(in + in_base + 3 * IN_K_STRIDE2);

    float s1x = ll.x + lh.x, s2x = hl.x + hh.x;
    float d1x = ll.x - lh.x, d2x = hl.x - hh.x;
    float s1y = ll.y + lh.y, s2y = hl.y + hh.y;
    float d1y = ll.y - lh.y, d2y = hl.y - hh.y;

    const float q = 0.25f;

    float4 r0 = make_float4((s1x + s2x) * q, (s1x - s2x) * q,
                            (s1y + s2y) * q, (s1y - s2y) * q);
    float4 r1 = make_float4((d1x + d2x) * q, (d1x - d2x) * q,
                            (d1y + d2y) * q, (d1y - d2y) * q);

    unsigned out_base = 2u * i - (i & (OW4 - 1));
    stcs4(out + out_base,       r0);
    stcs4(out + out_base + OW4, r1);
}

extern "C" void kernel_launch(void* const* d_in, const int* in_sizes, int n_in,
                              void* d_out, int out_size)
{
    const float2* in  = (const float2*)d_in[0];
    float4*       out = (float4*)d_out;

    const int threads = 256;
    const int blocks  = (int)(N_ITEMS / threads);   // 65536

    iwt_kernel<<<blocks, threads>>>(in, out);
}

// round 15
// speedup vs baseline: 1.0210x; 1.0008x over previous
#include <cuda_runtime.h>
#include <cuda_bf16.h>
#include <cstdint>

// Inverse 2x2 Haar synthesis — final form:
// 1 item/thread, 256-thread blocks, compact 2-op addressing,
// compiler-scheduled non-coherent loads (LDG.E.CONSTANT) + .cs streaming stores.
// Input  x: [B=8, 4*C=256, H=256, W=256] fp32  (subband-major: k*C + c)
// Output o: [B=8, C=64, 2H=512, 2W=512] fp32
//
// Work item i = b*2^21 + c*32768 + h*128 + j   (float2-granular, j<128)
//   in_base(float2)  = i + 3*(i & ~(2^21-1))
//   out_base(float4) = 2*i - (i & 127)
// Loads:  4 x LDG.64 (fully coalesced), Stores: 2 x STG.128 (fully coalesced)

static constexpr int      IN_K_STRIDE2 = 64 * 256 * 128;      // 2,097,152 float2
static constexpr int      OW4          = 128;                 // float4 per output row
static constexpr unsigned B_MASK       = ~((1u << 21) - 1u);
static constexpr unsigned N_ITEMS      = 16777216u;

__device__ __forceinline__ void stcs4(float4* p, float4 v) {
    asm volatile("st.global.cs.v4.f32 [%0], {%1, %2, %3, %4};"
                 :: "l"(p), "f"(v.x), "f"(v.y), "f"(v.z), "f"(v.w));
}

__global__ __launch_bounds__(256)
void iwt_kernel(const float2* __restrict__ in, float4* __restrict__ out)
{
    unsigned i = blockIdx.x * blockDim.x + threadIdx.x;   // < 2^24

    unsigned in_base = i + 3u * (i & B_MASK);

    // Plain dereference of const __restrict__ -> LDG.E.64.CONSTANT (nc path),
    // compiler free to batch/schedule.
    float2 ll = in[in_base + 0 * IN_K_STRIDE2];
    float2 lh = in[in_base + 1 * IN_K_STRIDE2];
    float2 hl = in[in_base + 2 * IN_K_STRIDE2];
    float2 hh = in[in_base + 3 * IN_K_STRIDE2];

    float s1x = ll.x + lh.x, s2x = hl.x + hh.x;
    float d1x = ll.x - lh.x, d2x = hl.x - hh.x;
    float s1y = ll.y + lh.y, s2y = hl.y + hh.y;
    float d1y = ll.y - lh.y, d2y = hl.y - hh.y;

    const float q = 0.25f;

    float4 r0 = make_float4((s1x + s2x) * q, (s1x - s2x) * q,
                            (s1y + s2y) * q, (s1y - s2y) * q);
    float4 r1 = make_float4((d1x + d2x) * q, (d1x - d2x) * q,
                            (d1y + d2y) * q, (d1y - d2y) * q);

    unsigned out_base = 2u * i - (i & (OW4 - 1));
    stcs4(out + out_base,       r0);
    stcs4(out + out_base + OW4, r1);
}

extern "C" void kernel_launch(void* const* d_in, const int* in_sizes, int n_in,
                              void* d_out, int out_size)
{
    const float2* in  = (const float2*)d_in[0];
    float4*       out = (float4*)d_out;

    const int threads = 256;
    const int blocks  = (int)(N_ITEMS / threads);   // 65536

    iwt_kernel<<<blocks, threads>>>(in, out);
}